// round 17
// baseline (speedup 1.0000x reference)
#include <cuda_runtime.h>
#include <cuda_bf16.h>
#include <math.h>
#include <stdint.h>
#include <stddef.h>

// ---------------- problem constants ----------------
#define NSEQ 8
#define SSEQ 448
#define DMODEL 768
#define MAXT 3584          // >= N*(S-1) = 3576
#define MAXV 50000
#define HTOT 640           // 256 + 128 + 128 + 128 concatenated head dims
#define ESCALE 16.0f       // emb quantization scale
#define EINV   0.0625f

// ---------------- device scratch (no allocs allowed) ----------------
__device__ __nv_bfloat16 g_Xb[MAXT * DMODEL];        // gathered predictor states bf16
__device__ __nv_bfloat16 g_Wb[HTOT * DMODEL];        // W^T concat bf16: [n=640][k=768]
__device__ float g_bc[HTOT];                         // concatenated transform biases
__device__ float g_H[MAXT * HTOT];                   // transform output fp32 (post-gelu/LN)
__device__ uint8_t g_H8[MAXT * HTOT];                // e4m3 copy of H (post-LN), scale 1
__device__ uint8_t g_E8[MAXV * 256];                 // e4m3 stem emb, x16
__device__ uint8_t g_E8p[200 * 128];                 // e4m3 pos emb, x16
__device__ uint8_t g_E8m[400 * 128];                 // e4m3 morph emb, x16
__device__ float g_se[4 * MAXT];                     // per-head per-row sum(exp(z))
__device__ float g_sl[4 * MAXT];                     // per-head per-row sum(z)
__device__ float g_tz[4 * MAXT];                     // per-head per-row target logit (captured)
__device__ float g_acc[16];                          // loss accumulators

// ---------------- asm helpers ----------------
#define CP_ASYNC16(dst, src) \
    asm volatile("cp.async.cg.shared.global [%0], [%1], 16;\n" :: "r"(dst), "l"(src))
#define CP_COMMIT() asm volatile("cp.async.commit_group;\n" ::)
#define CP_WAIT0()  asm volatile("cp.async.wait_group 0;\n" ::)
#define CP_WAIT1()  asm volatile("cp.async.wait_group 1;\n" ::)

__device__ __forceinline__ void ldsm_x4(uint32_t* r, uint32_t addr) {
    asm volatile("ldmatrix.sync.aligned.m8n8.x4.shared.b16 {%0,%1,%2,%3}, [%4];"
                 : "=r"(r[0]), "=r"(r[1]), "=r"(r[2]), "=r"(r[3]) : "r"(addr));
}

__device__ __forceinline__ void mma_bf16(float* c, const uint32_t* a, const uint32_t* b) {
    asm volatile("mma.sync.aligned.m16n8k16.row.col.f32.bf16.bf16.f32 "
                 "{%0,%1,%2,%3}, {%4,%5,%6,%7}, {%8,%9}, {%0,%1,%2,%3};\n"
                 : "+f"(c[0]), "+f"(c[1]), "+f"(c[2]), "+f"(c[3])
                 : "r"(a[0]), "r"(a[1]), "r"(a[2]), "r"(a[3]), "r"(b[0]), "r"(b[1]));
}

// FP8 e4m3 MMA: m16n8k32, fragments = m16n8k16-bf16 layout over u16 (=2 fp8) units
__device__ __forceinline__ void mma_e4m3(float* c, const uint32_t* a, const uint32_t* b) {
    asm volatile("mma.sync.aligned.m16n8k32.row.col.f32.e4m3.e4m3.f32 "
                 "{%0,%1,%2,%3}, {%4,%5,%6,%7}, {%8,%9}, {%0,%1,%2,%3};\n"
                 : "+f"(c[0]), "+f"(c[1]), "+f"(c[2]), "+f"(c[3])
                 : "r"(a[0]), "r"(a[1]), "r"(a[2]), "r"(a[3]), "r"(b[0]), "r"(b[1]));
}

__device__ __forceinline__ uint16_t f2x_e4m3(float hi, float lo) {
    uint16_t p;
    asm("cvt.rn.satfinite.e4m3x2.f32 %0, %1, %2;" : "=h"(p) : "f"(hi), "f"(lo));
    return p;
}

// ---- transform GEMM (bf16) staging ----
#define BKP 40                    // bf16 row stride (80 B)
#define STAGE_B (128 * BKP * 2)   // 10240 B

// ---- stats GEMM (fp8) staging: K-chunk = 128 fp8, row stride 144 B ----
#define RST8 144
#define RST8U 72                  // u16 units
#define STAGE8 (128 * RST8)       // 18432 B
#define SMEM_STATS8 (2 * STAGE8 * 2 + 2 * 4 * 128 * 4 + 128 * 4 + 128 * 4)  // +s_tgt

// bf16 stage loader
__device__ __forceinline__ void load_tile_pair(
    const __nv_bfloat16* __restrict__ A, int lda, int Arows, int m0,
    const __nv_bfloat16* __restrict__ B, int ldb, int Brows, int n0,
    int k0, uint32_t a_st, uint32_t b_st, int tid)
{
    #pragma unroll
    for (int i = 0; i < 2; i++) {
        int idx = tid + i * 256;
        int row = idx >> 2, c16 = idx & 3;
        int gm = m0 + row; if (gm >= Arows) gm = Arows - 1;
        CP_ASYNC16(a_st + (row * BKP + c16 * 8) * 2, A + (size_t)gm * lda + k0 + c16 * 8);
        int gn = n0 + row; if (gn >= Brows) gn = Brows - 1;
        CP_ASYNC16(b_st + (row * BKP + c16 * 8) * 2, B + (size_t)gn * ldb + k0 + c16 * 8);
    }
}

// fp8 chunk loader: 128 rows x 128 fp8 of A and B; 8 cp.async/thread
__device__ __forceinline__ void load_chunk8(
    const uint8_t* __restrict__ A, int lda, int Arows, int m0,
    const uint8_t* __restrict__ B, int ldb, int Brows, int n0,
    int k0, uint32_t a_st, uint32_t b_st, int tid)
{
    #pragma unroll
    for (int i = 0; i < 4; i++) {
        int idx = tid + i * 256;
        int row = idx >> 3, c = idx & 7;
        int gm = m0 + row; if (gm >= Arows) gm = Arows - 1;
        CP_ASYNC16(a_st + row * RST8 + c * 16, A + (size_t)gm * lda + k0 + c * 16);
        int gn = n0 + row; if (gn >= Brows) gn = Brows - 1;
        CP_ASYNC16(b_st + row * RST8 + c * 16, B + (size_t)gn * ldb + k0 + c * 16);
    }
}

// ---------------- fused prep: gather + W pack + emb fp8 + zero accumulators ---------------
__device__ __forceinline__ void cvt8(const float* __restrict__ s, uint8_t* __restrict__ d) {
    float4 v0 = *(const float4*)s;
    float4 v1 = *(const float4*)(s + 4);
    uint16_t p[4];
    p[0] = f2x_e4m3(v0.y * ESCALE, v0.x * ESCALE);
    p[1] = f2x_e4m3(v0.w * ESCALE, v0.z * ESCALE);
    p[2] = f2x_e4m3(v1.y * ESCALE, v1.x * ESCALE);
    p[3] = f2x_e4m3(v1.w * ESCALE, v1.z * ESCALE);
    *(uint64_t*)d = *(uint64_t*)p;
}

__global__ void prep_k(const float* __restrict__ hid, const int* __restrict__ hsel,
                       const float* __restrict__ Ws, const float* __restrict__ bs,
                       const float* __restrict__ Wp, const float* __restrict__ bp,
                       const float* __restrict__ Wm, const float* __restrict__ bm,
                       const float* __restrict__ Wa, const float* __restrict__ ba,
                       const float* __restrict__ se, const float* __restrict__ pe,
                       const float* __restrict__ me, int T) {
    int i = blockIdx.x * blockDim.x + threadIdx.x;
    int ng = T * 192;                        // gather float4 chunks
    const int nw = HTOT * DMODEL;            // W elements
    const int ne_s = 50000 * 256 / 8, ne_p = 200 * 128 / 8, ne_m = 400 * 128 / 8;
    if (i < ng) {
        int row = i / 192, j = i - row * 192;
        int idx = hsel[row];
        int s = idx % SSEQ, n = idx / SSEQ;
        float4 v = ((const float4*)(hid + ((size_t)s * NSEQ + n) * DMODEL))[j];
        __nv_bfloat16 o[4] = {__float2bfloat16_rn(v.x), __float2bfloat16_rn(v.y),
                              __float2bfloat16_rn(v.z), __float2bfloat16_rn(v.w)};
        *(uint64_t*)(g_Xb + (size_t)row * DMODEL + j * 4) = *(uint64_t*)o;
        return;
    }
    i -= ng;
    if (i < nw) {
        int n = i / DMODEL, k = i - n * DMODEL;
        const float* W; int Dh, off;
        if (n < 256)      { W = Ws; Dh = 256; off = 0; }
        else if (n < 384) { W = Wp; Dh = 128; off = 256; }
        else if (n < 512) { W = Wm; Dh = 128; off = 384; }
        else              { W = Wa; Dh = 128; off = 512; }
        g_Wb[(size_t)n * DMODEL + k] = __float2bfloat16_rn(W[(size_t)k * Dh + (n - off)]);
        if (i < HTOT) {
            const float* b; int boff;
            if (i < 256)      { b = bs; boff = 0; }
            else if (i < 384) { b = bp; boff = 256; }
            else if (i < 512) { b = bm; boff = 384; }
            else              { b = ba; boff = 512; }
            g_bc[i] = b[i - boff];
        }
        if (i < 16) g_acc[i] = 0.0f;
        if (i < 4 * MAXT) { g_se[i] = 0.0f; g_sl[i] = 0.0f; }
        return;
    }
    i -= nw;
    if (i < ne_s) { cvt8(se + (size_t)i * 8, g_E8 + (size_t)i * 8); return; }
    i -= ne_s;
    if (i < ne_p) { cvt8(pe + (size_t)i * 8, g_E8p + (size_t)i * 8); return; }
    i -= ne_p;
    if (i < ne_m) { cvt8(me + (size_t)i * 8, g_E8m + (size_t)i * 8); return; }
}

// ---------------- transform GEMM (bf16 TC): g_H = gelu(Xb @ Wb^T + bc), out stride 640 ----
__global__ void __launch_bounds__(256)
gemm_tc_gelu(int M) {
    __shared__ __align__(16) __nv_bfloat16 As[2][128 * BKP];
    __shared__ __align__(16) __nv_bfloat16 Bs[2][128 * BKP];
    int m0 = blockIdx.y * 128, n0 = blockIdx.x * 128;
    int tid = threadIdx.x;
    int warp = tid >> 5, lane = tid & 31;
    int wm = warp >> 2, wn = warp & 3;
    int gr = lane >> 2, gc = lane & 3;

    uint32_t a_base = (uint32_t)__cvta_generic_to_shared(&As[0][0]);
    uint32_t b_base = (uint32_t)__cvta_generic_to_shared(&Bs[0][0]);
    const uint32_t STAGE = 128 * BKP * 2;

    float acc[4][4][4];
    #pragma unroll
    for (int mf = 0; mf < 4; mf++)
        #pragma unroll
        for (int nf = 0; nf < 4; nf++)
            #pragma unroll
            for (int q = 0; q < 4; q++) acc[mf][nf][q] = 0.0f;

    const int nc = DMODEL / 32;   // 24
    load_tile_pair(g_Xb, DMODEL, M, m0, g_Wb, DMODEL, HTOT, n0, 0, a_base, b_base, tid);
    CP_COMMIT();

    int a_row_off = wm * 64 + ((lane >> 3) & 1) * 8 + (lane & 7);
    int a_col     = (lane >> 4) * 8;
    int b_row_off = wn * 32 + ((lane >> 4) & 1) * 8 + (lane & 7);
    int b_col     = ((lane >> 3) & 1) * 8;

    for (int c = 0; c < nc; c++) {
        int cur = c & 1;
        if (c + 1 < nc)
            load_tile_pair(g_Xb, DMODEL, M, m0, g_Wb, DMODEL, HTOT, n0,
                           (c + 1) << 5, a_base + (cur ^ 1) * STAGE, b_base + (cur ^ 1) * STAGE, tid);
        CP_COMMIT();
        CP_WAIT1();
        __syncthreads();
        uint32_t abase_s = a_base + cur * STAGE;
        uint32_t bbase_s = b_base + cur * STAGE;
        #pragma unroll
        for (int ks = 0; ks < 2; ks++) {
            uint32_t af[4][4], bf[2][4];
            #pragma unroll
            for (int mf = 0; mf < 4; mf++)
                ldsm_x4(af[mf], abase_s + ((a_row_off + mf * 16) * BKP + a_col + ks * 16) * 2);
            #pragma unroll
            for (int p = 0; p < 2; p++)
                ldsm_x4(bf[p], bbase_s + ((b_row_off + p * 16) * BKP + b_col + ks * 16) * 2);
            #pragma unroll
            for (int mf = 0; mf < 4; mf++)
                #pragma unroll
                for (int nf = 0; nf < 4; nf++)
                    mma_bf16(acc[mf][nf], af[mf], &bf[nf >> 1][(nf & 1) * 2]);
        }
        __syncthreads();
    }

    #pragma unroll
    for (int mf = 0; mf < 4; mf++) {
        #pragma unroll
        for (int h = 0; h < 2; h++) {
            int grow = m0 + wm * 64 + mf * 16 + h * 8 + gr;
            if (grow < M) {
                #pragma unroll
                for (int nf = 0; nf < 4; nf++) {
                    int col = n0 + wn * 32 + nf * 8 + gc * 2;
                    float z0 = acc[mf][nf][h * 2 + 0] + g_bc[col];
                    float z1 = acc[mf][nf][h * 2 + 1] + g_bc[col + 1];
                    float y0 = 0.5f * z0 * (1.0f + erff(z0 * 0.70710678118654752f));
                    float y1 = 0.5f * z1 * (1.0f + erff(z1 * 0.70710678118654752f));
                    *(float2*)(g_H + (size_t)grow * HTOT + col) = make_float2(y0, y1);
                }
            }
        }
    }
}

// ---------------- merged LayerNorm: one warp per (row, head); writes fp32 + e4m3 ----------
__global__ void ln_all_k(const float* __restrict__ gs, const float* __restrict__ bts,
                         const float* __restrict__ gp, const float* __restrict__ btp,
                         const float* __restrict__ gm, const float* __restrict__ btm,
                         const float* __restrict__ ga, const float* __restrict__ bta,
                         int T) {
    int w = threadIdx.x >> 5, lane = threadIdx.x & 31;
    int task = blockIdx.x * 8 + w;
    if (task >= 4 * T) return;
    int head = task / T;
    int row = task - head * T;
    int hoff, DH;
    const float* g; const float* bt;
    if (head == 0)      { hoff = 0;   DH = 256; g = gs; bt = bts; }
    else if (head == 1) { hoff = 256; DH = 128; g = gp; bt = btp; }
    else if (head == 2) { hoff = 384; DH = 128; g = gm; bt = btm; }
    else                { hoff = 512; DH = 128; g = ga; bt = bta; }
    int E = DH >> 5;
    float* base = g_H + (size_t)row * HTOT + hoff;
    float v[8];
    float s = 0.f;
    for (int i = 0; i < E; i++) { v[i] = base[lane + i * 32]; s += v[i]; }
    #pragma unroll
    for (int o = 16; o > 0; o >>= 1) s += __shfl_xor_sync(0xffffffffu, s, o);
    float mean = s / (float)DH;
    float q = 0.f;
    for (int i = 0; i < E; i++) { float d = v[i] - mean; q += d * d; }
    #pragma unroll
    for (int o = 16; o > 0; o >>= 1) q += __shfl_xor_sync(0xffffffffu, q, o);
    float r = rsqrtf(q / (float)DH + 1e-12f);
    for (int i = 0; i < E; i++) {
        float y = (v[i] - mean) * r * g[lane + i * 32] + bt[lane + i * 32];
        base[lane + i * 32] = y;
        g_H8[(size_t)row * HTOT + hoff + lane + i * 32] = (uint8_t)f2x_e4m3(0.f, y);
    }
}

// ---------------- per-block stats GEMM body (fp8, K-chunks of 128, tz capture) ------------
__device__ void stats_block(int nIdx, int mIdx,
                            const uint8_t* __restrict__ A, const uint8_t* __restrict__ E,
                            const float* __restrict__ vbias,
                            const int* __restrict__ labels, const int* __restrict__ tsel,
                            int M, int V, int K, int head) {
    extern __shared__ __align__(16) char dyn[];
    float* s_s   = (float*)(dyn + 2 * STAGE8 * 2);
    float* s_l   = s_s + 4 * 128;
    float* s_bias = s_l + 4 * 128;
    int*   s_tgt = (int*)(s_bias + 128);

    int m0 = mIdx * 128, n0 = nIdx * 128;
    int tid = threadIdx.x;
    int warp = tid >> 5, lane = tid & 31;
    int wm = warp >> 2, wn = warp & 3;
    int gr = lane >> 2, gc = lane & 3;

    if (tid < 128) {
        int v = n0 + tid;
        s_bias[tid] = (v < V) ? vbias[v] : 0.0f;
        int grow = m0 + tid;
        s_tgt[tid] = (grow < M) ? labels[tsel[grow]] : -1;
    }

    uint32_t a_base = (uint32_t)__cvta_generic_to_shared(dyn);
    uint32_t b_base = a_base + 2 * STAGE8;

    float acc[4][4][4];
    #pragma unroll
    for (int mf = 0; mf < 4; mf++)
        #pragma unroll
        for (int nf = 0; nf < 4; nf++)
            #pragma unroll
            for (int q = 0; q < 4; q++) acc[mf][nf][q] = 0.0f;

    int nc = K >> 7;

    load_chunk8(A, HTOT, M, m0, E, K, V, n0, 0, a_base, b_base, tid);
    CP_COMMIT();

    int a_row_off = wm * 64 + ((lane >> 3) & 1) * 8 + (lane & 7);
    int a_col     = (lane >> 4) * 8;
    int b_row_off = wn * 32 + ((lane >> 4) & 1) * 8 + (lane & 7);
    int b_col     = ((lane >> 3) & 1) * 8;

    for (int c = 0; c < nc; c++) {
        if (c + 1 < nc) {
            load_chunk8(A, HTOT, M, m0, E, K, V, n0, (c + 1) << 7,
                        a_base + ((c + 1) & 1) * STAGE8, b_base + ((c + 1) & 1) * STAGE8, tid);
            CP_COMMIT();
            CP_WAIT1();
        } else {
            CP_WAIT0();
        }
        __syncthreads();
        uint32_t abase_s = a_base + (c & 1) * STAGE8;
        uint32_t bbase_s = b_base + (c & 1) * STAGE8;
        #pragma unroll
        for (int ks = 0; ks < 4; ks++) {
            uint32_t af[4][4], bf[2][4];
            #pragma unroll
            for (int mf = 0; mf < 4; mf++)
                ldsm_x4(af[mf], abase_s + ((a_row_off + mf * 16) * RST8U + a_col + ks * 16) * 2);
            #pragma unroll
            for (int p = 0; p < 2; p++)
                ldsm_x4(bf[p], bbase_s + ((b_row_off + p * 16) * RST8U + b_col + ks * 16) * 2);
            #pragma unroll
            for (int mf = 0; mf < 4; mf++)
                #pragma unroll
                for (int nf = 0; nf < 4; nf++)
                    mma_e4m3(acc[mf][nf], af[mf], &bf[nf >> 1][(nf & 1) * 2]);
        }
    }

    __syncthreads();
    #pragma unroll
    for (int mf = 0; mf < 4; mf++) {
        #pragma unroll
        for (int h = 0; h < 2; h++) {
            int rowb = wm * 64 + mf * 16 + h * 8 + gr;
            int tgt = s_tgt[rowb];
            float sloc = 0.f, slloc = 0.f;
            #pragma unroll
            for (int nf = 0; nf < 4; nf++) {
                #pragma unroll
                for (int q = 0; q < 2; q++) {
                    int colb = wn * 32 + nf * 8 + gc * 2 + q;
                    if (n0 + colb < V) {
                        float z = acc[mf][nf][h * 2 + q] * EINV + s_bias[colb];
                        sloc += __expf(z);
                        slloc += z;
                        if (n0 + colb == tgt)
                            g_tz[head * MAXT + m0 + rowb] = z;
                    }
                }
            }
            sloc  += __shfl_xor_sync(0xffffffffu, sloc, 1);
            sloc  += __shfl_xor_sync(0xffffffffu, sloc, 2);
            slloc += __shfl_xor_sync(0xffffffffu, slloc, 1);
            slloc += __shfl_xor_sync(0xffffffffu, slloc, 2);
            if (gc == 0) {
                s_s[wn * 128 + rowb] = sloc;
                s_l[wn * 128 + rowb] = slloc;
            }
        }
    }
    __syncthreads();
    if (tid < 128) {
        int grow = m0 + tid;
        if (grow < M) {
            float s = s_s[tid] + s_s[128 + tid] + s_s[256 + tid] + s_s[384 + tid];
            float sl = s_l[tid] + s_l[128 + tid] + s_l[256 + tid] + s_l[384 + tid];
            atomicAdd(&g_se[head * MAXT + grow], s);
            atomicAdd(&g_sl[head * MAXT + grow], sl);
        }
    }
}

// ---------------- per-block BCE body (fp32 SIMT, 64x64 tiles) ----------------
__device__ void bce_block(int nIdx, int mIdx,
                          const float* __restrict__ emb, const float* __restrict__ vbias,
                          const float* __restrict__ aprob, const int* __restrict__ tsel,
                          const int* __restrict__ asel, int M, int V, int K, int hoff) {
    extern __shared__ __align__(16) char dyn[];
    float (*As)[68] = (float(*)[68])dyn;
    float (*Bs)[68] = (float(*)[68])(dyn + 16 * 68 * 4);
    float* red = (float*)(dyn + 2 * 16 * 68 * 4);
    int m0 = mIdx * 64, n0 = nIdx * 64;
    int tid = threadIdx.x;
    int tx = tid & 15, ty = tid >> 4;
    int lrow = tid >> 2, lk4 = (tid & 3) * 4;
    float acc[4][4] = {};
    for (int k0 = 0; k0 < K; k0 += 16) {
        float4 av = make_float4(0.f, 0.f, 0.f, 0.f);
        int ar = m0 + lrow;
        if (ar < M) {
            int pr = asel[ar];
            av = *(const float4*)(g_H + (size_t)pr * HTOT + hoff + k0 + lk4);
        }
        As[lk4 + 0][lrow] = av.x; As[lk4 + 1][lrow] = av.y;
        As[lk4 + 2][lrow] = av.z; As[lk4 + 3][lrow] = av.w;
        float4 bv = make_float4(0.f, 0.f, 0.f, 0.f);
        int br = n0 + lrow;
        if (br < V) bv = *(const float4*)(emb + (size_t)br * K + k0 + lk4);
        Bs[lk4 + 0][lrow] = bv.x; Bs[lk4 + 1][lrow] = bv.y;
        Bs[lk4 + 2][lrow] = bv.z; Bs[lk4 + 3][lrow] = bv.w;
        __syncthreads();
        #pragma unroll
        for (int k = 0; k < 16; k++) {
            float4 a4 = *(const float4*)&As[k][ty * 4];
            float4 b4 = *(const float4*)&Bs[k][tx * 4];
            float a_[4] = {a4.x, a4.y, a4.z, a4.w};
            float b_[4] = {b4.x, b4.y, b4.z, b4.w};
            #pragma unroll
            for (int r = 0; r < 4; r++)
                #pragma unroll
                for (int c = 0; c < 4; c++) acc[r][c] += a_[r] * b_[c];
        }
        __syncthreads();
    }
    float lsum = 0.f;
    #pragma unroll
    for (int r = 0; r < 4; r++) {
        int grow = m0 + ty * 4 + r;
        if (grow < M) {
            int trow = tsel[asel[grow]];
            #pragma unroll
            for (int c = 0; c < 4; c++) {
                int v = n0 + tx * 4 + c;
                if (v < V) {
                    float z = acc[r][c] + vbias[v];
                    float t = aprob[(size_t)trow * 360 + v];
                    lsum += fmaxf(z, 0.f) - z * t + log1pf(__expf(-fabsf(z)));
                }
            }
        }
    }
    red[tid] = lsum; __syncthreads();
    for (int o = 128; o > 0; o >>= 1) { if (tid < o) red[tid] += red[tid + o]; __syncthreads(); }
    if (tid == 0) atomicAdd(&g_acc[6], red[0]);
}

// ---------------- MEGA kernel: BCE + pos/morph/stem stats in ONE launch -------------------
__global__ void __launch_bounds__(256, 2)
mega_heads_k(const float* __restrict__ stem_bias, const float* __restrict__ pos_bias,
             const float* __restrict__ morph_bias,
             const float* __restrict__ aff_emb, const float* __restrict__ aff_bias,
             const float* __restrict__ aprob,
             const int* __restrict__ stems, const int* __restrict__ postags,
             const int* __restrict__ morphs,
             const int* __restrict__ tsel, const int* __restrict__ asel,
             int T, int Ta, int mT, int mTa, int nvb_s) {
    int b = blockIdx.x;
    int nbb = 6 * mTa;
    if (b < nbb) {
        bce_block(b % 6, b / 6, aff_emb, aff_bias, aprob, tsel, asel, Ta, 360, 128, 512);
        return;
    }
    b -= nbb;
    if (b < 2 * mT) {
        stats_block(b % 2, b / 2, g_H8 + 256, g_E8p, pos_bias, postags, tsel, T, 200, 128, 1);
        return;
    }
    b -= 2 * mT;
    if (b < 4 * mT) {
        stats_block(b % 4, b / 4, g_H8 + 384, g_E8m, morph_bias, morphs, tsel, T, 400, 128, 2);
        return;
    }
    b -= 4 * mT;
    stats_block(b % nvb_s, b / nvb_s, g_H8, g_E8, stem_bias, stems, tsel, T, 50000, 256, 0);
}

// ---------------- per-row nll accumulation (target logit already captured) ----------------
__global__ void nll_k(int T) {
    int i = blockIdx.x * blockDim.x + threadIdx.x;
    if (i >= 3 * T) return;
    int head = i / T, row = i - head * T;
    const int Vs[3] = {50000, 200, 400};
    float logZ = logf(g_se[head * MAXT + row]);
    float nll = logZ - g_tz[head * MAXT + row];
    float smooth = (float)Vs[head] * logZ - g_sl[head * MAXT + row];
    atomicAdd(&g_acc[head * 2], nll);
    atomicAdd(&g_acc[head * 2 + 1], smooth);
}

// ---------------- finalize: assemble the 7 output scalars ----------------
__global__ void finalize_k(float* __restrict__ out, int T, int Ta) {
    if (threadIdx.x != 0 || blockIdx.x != 0) return;
    const int Vs[3] = {50000, 200, 400};
    for (int h = 0; h < 3; h++) {
        float nll_m = g_acc[2 * h] / (float)T;
        float sm_m  = g_acc[2 * h + 1] / (float)T;
        float eps_i = 0.1f / (float)(Vs[h] - 1);
        out[h] = (1.0f - 0.1f - eps_i) * nll_m + eps_i * sm_m;
        out[4 + h] = nll_m;
    }
    out[3] = g_acc[6] / ((float)Ta * 360.0f);
}

// ---------------- launch ----------------
extern "C" void kernel_launch(void* const* d_in, const int* in_sizes, int n_in,
                              void* d_out, int out_size) {
    const float* hid    = (const float*)d_in[0];
    const float* aprob  = (const float*)d_in[1];
    const int* stems    = (const int*)d_in[2];
    const int* postags  = (const int*)d_in[3];
    const int* morphs   = (const int*)d_in[4];
    const int* hsel     = (const int*)d_in[5];
    const int* tsel     = (const int*)d_in[6];
    const int* asel     = (const int*)d_in[7];
    const float* stem_emb  = (const float*)d_in[8];
    const float* stem_W    = (const float*)d_in[9];
    const float* stem_b    = (const float*)d_in[10];
    const float* stem_g    = (const float*)d_in[11];
    const float* stem_beta = (const float*)d_in[12];
    const float* stem_bias = (const float*)d_in[13];
    const float* pos_emb   = (const float*)d_in[14];
    const float* pos_W     = (const float*)d_in[15];
    const float* pos_b     = (const float*)d_in[16];
    const float* pos_g     = (const float*)d_in[17];
    const float* pos_beta  = (const float*)d_in[18];
    const float* pos_bias  = (const float*)d_in[19];
    const float* morph_emb = (const float*)d_in[20];
    const float* morph_W   = (const float*)d_in[21];
    const float* morph_b   = (const float*)d_in[22];
    const float* morph_g   = (const float*)d_in[23];
    const float* morph_beta= (const float*)d_in[24];
    const float* morph_bias= (const float*)d_in[25];
    const float* aff_emb   = (const float*)d_in[26];
    const float* aff_W     = (const float*)d_in[27];
    const float* aff_b     = (const float*)d_in[28];
    const float* aff_g     = (const float*)d_in[29];
    const float* aff_beta  = (const float*)d_in[30];
    const float* aff_bias  = (const float*)d_in[31];
    float* out = (float*)d_out;

    int T  = in_sizes[5];
    int Ta = in_sizes[7];
    int mT128 = (T + 127) / 128;
    int mTa = (Ta + 63) / 64;
    const int nvb_s = (50000 + 127) / 128;   // 391

    cudaFuncSetAttribute(mega_heads_k,
                         cudaFuncAttributeMaxDynamicSharedMemorySize, SMEM_STATS8);

    // fused prep: gather + W pack + emb fp8 converts + zero accumulators
    {
        int ntot = T * 192 + HTOT * DMODEL
                 + 50000 * 256 / 8 + 200 * 128 / 8 + 400 * 128 / 8;
        prep_k<<<(ntot + 255) / 256, 256>>>(hid, hsel, stem_W, stem_b, pos_W, pos_b,
                                            morph_W, morph_b, aff_W, aff_b,
                                            stem_emb, pos_emb, morph_emb, T);
    }

    gemm_tc_gelu<<<dim3(HTOT / 128, mT128), 256>>>(T);
    ln_all_k<<<(4 * T + 7) / 8, 256>>>(stem_g, stem_beta, pos_g, pos_beta,
                                       morph_g, morph_beta, aff_g, aff_beta, T);

    // single mega launch: BCE + pos + morph + stem stats (with target-logit capture)
    {
        int nblocks = 6 * mTa + 2 * mT128 + 4 * mT128 + nvb_s * mT128;
        mega_heads_k<<<nblocks, 256, SMEM_STATS8>>>(stem_bias, pos_bias, morph_bias,
                                                    aff_emb, aff_bias, aprob,
                                                    stems, postags, morphs, tsel, asel,
                                                    T, Ta, mT128, mTa, nvb_s);
    }

    nll_k<<<(3 * T + 255) / 256, 256>>>(T);
    finalize_k<<<1, 32>>>(out, T, Ta);
}